// round 15
// baseline (speedup 1.0000x reference)
#include <cuda_runtime.h>
#include <math.h>

#define BATCH 8
#define TLEN 120000
#define NF 1001
#define FFTL 2048
#define HALF 1024
#define K1 1025
#define KPAD 36
#define CLEN 1097          /* K1 + 2*KPAD */
#define NTH 512
#define SBT 256            /* threads per sub-block (frame) */
#define PIF 3.14159265358979f

/* dynamic smem layout (bytes):
   za  float2[2][1024] @ 0      (16384)
   zb  float2[2][1024] @ 16384  (16384)  -- sC alias during cumsum
   tw3 float2[504]     @ 32768  (4032)
   sP  float[2][1032]  @ 36800  (8256)
   wex float[2][8]     @ 45056  (64)
   red float[2][24]    @ 45120  (192)
   scl float[2][4]     @ 45312  (32)
   total 45344 -> 4 CTAs/SM */
#define SMEM_BYTES 45344

typedef unsigned long long u64;

__device__ float2 g_tw3[504];   // 126 (w1,w2,w3,pad) triples
__device__ float2 g_twu[257];   // e^{-i pi k/512}, k=0..256
__device__ float  g_sinb[513];  // sin(pi n/1024), n=0..512
__device__ float  g_invk[1025];

__global__ void init_tables() {
    int i = blockIdx.x * blockDim.x + threadIdx.x;
    if (i <= 1024) g_invk[i] = (i == 0) ? 0.0f : 1.0f / (float)i;
    if (i <= 256) {
        float s, c; sincospif(-(float)i * (1.0f / 512.0f), &s, &c);
        g_twu[i] = make_float2(c, s);
    }
    if (i <= 512) g_sinb[i] = sinpif((float)i * (1.0f / 1024.0f));
    if (i < 126) {
        float ang;  // w1 angle in units of pi
        if (i < 64)       ang = (float)(4 * i)          * (1.0f / 512.0f);
        else if (i < 80)  ang = (float)(16 * (i - 64))  * (1.0f / 512.0f);
        else if (i < 84)  ang = (float)(64 * (i - 80))  * (1.0f / 512.0f);
        else if (i < 116) ang = (float)(4 * (i - 84))   * (1.0f / 256.0f);
        else if (i < 124) ang = (float)(16 * (i - 116)) * (1.0f / 256.0f);
        else              ang = (float)(64 * (i - 124)) * (1.0f / 256.0f);
        float s1, c1, s2, c2, s3, c3;
        sincospif(-ang, &s1, &c1);
        sincospif(-2.0f * ang, &s2, &c2);
        sincospif(-3.0f * ang, &s3, &c3);
        g_tw3[4 * i]     = make_float2(c1, s1);
        g_tw3[4 * i + 1] = make_float2(c2, s2);
        g_tw3[4 * i + 2] = make_float2(c3, s3);
        g_tw3[4 * i + 3] = make_float2(0.f, 0.f);
    }
}

__device__ __forceinline__ float warp_sum(float v) {
#pragma unroll
    for (int o = 16; o; o >>= 1) v += __shfl_down_sync(0xffffffffu, v, o);
    return v;
}

__device__ __forceinline__ float2 cmul(float2 a, float2 b) {
    return make_float2(a.x * b.x - a.y * b.y, a.x * b.y + a.y * b.x);
}

__device__ __forceinline__ float2 padd(float2 a, float2 b) {
    float2 r;
    asm("{\n\t.reg .b64 ra, rb, rc;\n\t"
        "mov.b64 ra, {%2, %3};\n\t"
        "mov.b64 rb, {%4, %5};\n\t"
        "add.rn.f32x2 rc, ra, rb;\n\t"
        "mov.b64 {%0, %1}, rc;\n\t}"
        : "=f"(r.x), "=f"(r.y)
        : "f"(a.x), "f"(a.y), "f"(b.x), "f"(b.y));
    return r;
}

__device__ __forceinline__ float2 psub(float2 a, float2 b, u64 neg1) {
    float2 r;
    asm("{\n\t.reg .b64 ra, rb, rc;\n\t"
        "mov.b64 ra, {%2, %3};\n\t"
        "mov.b64 rb, {%4, %5};\n\t"
        "fma.rn.f32x2 rc, rb, %6, ra;\n\t"
        "mov.b64 {%0, %1}, rc;\n\t}"
        : "=f"(r.x), "=f"(r.y)
        : "f"(a.x), "f"(a.y), "f"(b.x), "f"(b.y), "l"(neg1));
    return r;
}

#define NEG1PK 0xBF800000BF800000ull

__device__ __forceinline__ int refl_idx(int t) {
    int j = t - KPAD;
    int r = j < 0 ? -j : j;
    if (r > HALF) r = FFTL - r;
    return r;
}

// radix-4 butterfly, stride 256 (1024-pt FFT)
__device__ __forceinline__ void bfly4(const float2* X, float2* Y, int r, int m,
                                      float2 w1, float2 w2, float2 w3) {
    const u64 n1 = NEG1PK;
    int q = r & (m - 1);
    int base = 4 * (r - q) + q;
    float2 a0 = X[r], a1 = X[r + 256], a2 = X[r + 512], a3 = X[r + 768];
    float2 b0 = padd(a0, a2), b1 = psub(a0, a2, n1);
    float2 b2 = padd(a1, a3), b3 = psub(a1, a3, n1);
    float2 t1 = make_float2(b1.x + b3.y, b1.y - b3.x);
    float2 t3 = make_float2(b1.x - b3.y, b1.y + b3.x);
    Y[base]         = padd(b0, b2);
    Y[base + m]     = cmul(t1, w1);
    Y[base + 2 * m] = cmul(psub(b0, b2, n1), w2);
    Y[base + 3 * m] = cmul(t3, w3);
}

// radix-4 butterfly, stride 128 (512-pt FFT)
__device__ __forceinline__ void bfly4s(const float2* X, float2* Y, int r, int m,
                                       float2 w1, float2 w2, float2 w3) {
    const u64 n1 = NEG1PK;
    int q = r & (m - 1);
    int base = 4 * (r - q) + q;
    float2 a0 = X[r], a1 = X[r + 128], a2 = X[r + 256], a3 = X[r + 384];
    float2 b0 = padd(a0, a2), b1 = psub(a0, a2, n1);
    float2 b2 = padd(a1, a3), b3 = psub(a1, a3, n1);
    float2 t1 = make_float2(b1.x + b3.y, b1.y - b3.x);
    float2 t3 = make_float2(b1.x - b3.y, b1.y + b3.x);
    Y[base]         = padd(b0, b2);
    Y[base + m]     = cmul(t1, w1);
    Y[base + 2 * m] = cmul(psub(b0, b2, n1), w2);
    Y[base + 3 * m] = cmul(t3, w3);
}

// Full 1024-pt complex FFT, radix-4 Stockham, 256 threads, 5 stages.
// Input in za, result in zb. w1s0 = per-thread stage-0 twiddle.
__device__ __forceinline__ void fft1024r4(float2* za, float2* zb,
                                          const float2* __restrict__ tw3,
                                          float2 w1s0, int r) {
    {   // stage 0: m=1, twiddle from registers
        float2 w1 = w1s0;
        float2 w2 = make_float2(w1.x * w1.x - w1.y * w1.y, 2.0f * w1.x * w1.y);
        float2 w3 = cmul(w1, w2);
        bfly4(za, zb, r, 1, w1, w2, w3);
    }
    __syncthreads();
    {
        int e = r >> 2;
        float4 w12 = ((const float4*)tw3)[2 * e];
        bfly4(zb, za, r, 4, make_float2(w12.x, w12.y), make_float2(w12.z, w12.w),
              tw3[4 * e + 2]);
    }
    __syncthreads();
    {
        int e = 64 + (r >> 4);
        float4 w12 = ((const float4*)tw3)[2 * e];
        bfly4(za, zb, r, 16, make_float2(w12.x, w12.y), make_float2(w12.z, w12.w),
              tw3[4 * e + 2]);
    }
    __syncthreads();
    {
        int e = 80 + (r >> 6);
        float4 w12 = ((const float4*)tw3)[2 * e];
        bfly4(zb, za, r, 64, make_float2(w12.x, w12.y), make_float2(w12.z, w12.w),
              tw3[4 * e + 2]);
    }
    __syncthreads();
    {   // stage 4: twiddles all 1
        const u64 n1 = NEG1PK;
        float2 a0 = za[r], a1 = za[r + 256], a2 = za[r + 512], a3 = za[r + 768];
        float2 b0 = padd(a0, a2), b1 = psub(a0, a2, n1);
        float2 b2 = padd(a1, a3), b3 = psub(a1, a3, n1);
        zb[r]       = padd(b0, b2);
        zb[r + 256] = make_float2(b1.x + b3.y, b1.y - b3.x);
        zb[r + 512] = psub(b0, b2, n1);
        zb[r + 768] = make_float2(b1.x - b3.y, b1.y + b3.x);
    }
    __syncthreads();
}

// Full 512-pt complex FFT: 4 radix-4 stages + final radix-2 (twiddle-free).
// Active on st<128; ALL threads must call (barriers inside). Result in zb.
__device__ __forceinline__ void fft512(float2* za, float2* zb,
                                       const float2* __restrict__ tw3, int st) {
    if (st < 128) {
        float2 w1 = __ldg(&g_twu[2 * st]);   // e^{-i pi st/256}
        float2 w2 = make_float2(w1.x * w1.x - w1.y * w1.y, 2.0f * w1.x * w1.y);
        float2 w3 = cmul(w1, w2);
        bfly4s(za, zb, st, 1, w1, w2, w3);
    }
    __syncthreads();
    if (st < 128) {
        int e = 84 + (st >> 2);
        float4 w12 = ((const float4*)tw3)[2 * e];
        bfly4s(zb, za, st, 4, make_float2(w12.x, w12.y), make_float2(w12.z, w12.w),
               tw3[4 * e + 2]);
    }
    __syncthreads();
    if (st < 128) {
        int e = 116 + (st >> 4);
        float4 w12 = ((const float4*)tw3)[2 * e];
        bfly4s(za, zb, st, 16, make_float2(w12.x, w12.y), make_float2(w12.z, w12.w),
               tw3[4 * e + 2]);
    }
    __syncthreads();
    if (st < 128) {
        int e = 124 + (st >> 6);
        float4 w12 = ((const float4*)tw3)[2 * e];
        bfly4s(zb, za, st, 64, make_float2(w12.x, w12.y), make_float2(w12.z, w12.w),
               tw3[4 * e + 2]);
    }
    __syncthreads();
    if (st < 128) {  // final radix-2, m=256, j=0 -> twiddle 1
        const u64 n1 = NEG1PK;
        float2 a0 = za[st],       c0 = za[st + 256];
        float2 a1 = za[st + 128], c1 = za[st + 384];
        zb[st]       = padd(a0, c0);
        zb[st + 256] = psub(a0, c0, n1);
        zb[st + 128] = padd(a1, c1);
        zb[st + 384] = psub(a1, c1, n1);
    }
    __syncthreads();
}

__device__ __forceinline__ float interpC(const float* __restrict__ C, float pos) {
    int lo = (int)floorf(pos);
    lo = min(max(lo, 0), CLEN - 2);
    float frac = pos - (float)lo;
    float clo = C[lo];
    return clo + (C[lo + 1] - clo) * frac;
}

// smoothed log-power at bin k, computed straight from the cumsum buffer.
__device__ __forceinline__ float smoothG(const float* __restrict__ sC, int k,
                                         float wbins, float invwidth, float linpart) {
    float plo = (float)k - 0.5f * wbins + ((float)KPAD - 0.5f);
    float phi = plo + wbins;
    float Ps = (interpC(sC, phi) - interpC(sC, plo) + linpart) * invwidth;
    return __logf(fmaxf(Ps, 1e-30f));
}

__global__ __launch_bounds__(NTH, 4)
void cheaptrick_kernel(const float* __restrict__ x, const float* __restrict__ f0in,
                       float* __restrict__ out) {
    extern __shared__ char smem[];

    const int tid  = threadIdx.x;
    const int sub  = tid >> 8;
    const int st   = tid & 255;
    const int lane = tid & 31;
    const int w8   = st >> 5;
    const int bx   = blockIdx.x;
    const int b    = blockIdx.y;

    float2* za  = (float2*)(smem)          + sub * 1024;
    float2* zb  = (float2*)(smem + 16384)  + sub * 1024;
    float2* tw3 = (float2*)(smem + 32768);
    float*  sP  = (float*)(smem + 36800)   + sub * 1032;
    float*  wex = (float*)(smem + 45056)   + sub * 8;
    float*  red = (float*)(smem + 45120)   + sub * 24;
    float*  scl = (float*)(smem + 45312)   + sub * 4;
    float*  sC  = (float*)(smem + 16384)   + sub * 2048;   // aliases zb
    float*  zaf = (float*)za;

    int fi = bx * 2 + sub;
    const bool dostore = (fi < NF);
    if (!dostore) fi = NF - 1;

    float f0v = f0in[b * NF + fi];
    if (f0v <= 35.2078239f) f0v = 500.0f;   // F_MIN = 72000/2045

    // per-thread twiddles for the 1024-pt FFT + its untangle
    float2 wst, w1s0, wq;
    {
        float c, s;
        sincospif(-(float)st * (1.0f / 1024.0f), &s, &c);
        wst  = make_float2(c, s);
        w1s0 = make_float2(c * c - s * s, 2.0f * c * s);
        const float R2 = 0.70710678118654752f;
        wq   = cmul(wst, make_float2(R2, -R2));
    }

    for (int r = tid; r < 504; r += NTH) tw3[r] = g_tw3[r];

    // -------- frame load + window (rotation recurrence) + sums ---------------
    const float hwl = rintf(36000.0f / f0v);
    const float f0n = f0v * (1.0f / 36000.0f);
    float cb, sb, cd, sd;
    sincospif((float)(st - HALF) * f0n, &sb, &cb);
    sincospif(256.0f * f0n, &sd, &cd);
    float s1 = 0.f, s2 = 0.f, s3 = 0.f;
    {
        float c0 = cb, s0 = sb;
#pragma unroll
        for (int ii = 0; ii < 8; ii++) {
            int i = st + ii * 256;
            int rel = i - HALF;
            int ix = min(max(fi * 120 + rel, 0), TLEN - 1);
            float v = x[b * TLEN + ix];
            float w = (fabsf((float)rel) <= hwl) ? fmaf(0.5f, c0, 0.5f) : 0.0f;
            zaf[i] = v * w;
            s1 += w; s2 += w * w; s3 += v * w;
            float cn = c0 * cd - s0 * sd;
            s0 = s0 * cd + c0 * sd;
            c0 = cn;
        }
    }
    s1 = warp_sum(s1); s2 = warp_sum(s2); s3 = warp_sum(s3);
    if (lane == 0) { red[w8] = s1; red[8 + w8] = s2; red[16 + w8] = s3; }
    __syncthreads();
    if (st == 0) {
        float a = 0.f, bb = 0.f, c = 0.f;
#pragma unroll
        for (int i = 0; i < 8; i++) { a += red[i]; bb += red[8 + i]; c += red[16 + i]; }
        scl[0] = a; scl[1] = bb; scl[2] = c;
    }
    __syncthreads();
    const float invs = 1.0f / sqrtf(scl[1]);
    const float mu   = scl[2] / scl[0];

    // -------- pack in place: wav = (v*w - mu*w)*invs (w replayed from regs) --
    {
        float c0 = cb, s0 = sb;
#pragma unroll
        for (int ii = 0; ii < 8; ii++) {
            int i = st + ii * 256;
            int rel = i - HALF;
            float w = (fabsf((float)rel) <= hwl) ? fmaf(0.5f, c0, 0.5f) : 0.0f;
            zaf[i] = (zaf[i] - mu * w) * invs;
            float cn = c0 * cd - s0 * sd;
            s0 = s0 * cd + c0 * sd;
            c0 = cn;
        }
    }
    __syncthreads();

    fft1024r4(za, zb, tw3, w1s0, st);   // result in zb

    // -------- paired untangle -> power spectrum ------------------------------
#pragma unroll
    for (int ii = 0; ii < 2; ii++) {
        int k = st + ii * 256;
        float2 w = (ii == 0) ? wst : wq;
        float2 Zk = zb[k];
        float2 Zm = zb[(1024 - k) & 1023];
        float Er = 0.5f * (Zk.x + Zm.x);
        float Ei = 0.5f * (Zk.y - Zm.y);
        float Or = 0.5f * (Zk.y + Zm.y);
        float Oi = 0.5f * (Zm.x - Zk.x);
        float u = w.x * Or - w.y * Oi;
        float t = w.x * Oi + w.y * Or;
        float XrP = Er + u, XiP = Ei + t;
        float XrM = Er - u, XiM = Ei - t;
        sP[k]        = XrP * XrP + XiP * XiP;
        sP[1024 - k] = XrM * XrM + XiM * XiM;
    }
    if (st == 0) { float2 Z = zb[512]; sP[512] = Z.x * Z.x + Z.y * Z.y; }
    __syncthreads();

    // -------- DC-band replication -------------------------------------------
    const float rate = f0v * (2048.0f / 24000.0f);
    const int  kmax  = (int)floorf(rate);
    float repl = 0.f;
    const bool dorep = (st <= kmax);
    if (dorep) {
        float m = rate - (float)st;
        int lo = (int)floorf(m);
        lo = min(max(lo, 0), K1 - 2);
        float fc = m - (float)lo;
        repl = sP[lo] * (1.f - fc) + sP[lo + 1] * fc;
    }
    __syncthreads();
    if (dorep) sP[st] += repl;
    __syncthreads();

    // -------- reflected cumsum, f32 with mean removal (sC aliases zb) --------
    float meanq;
    {
        const float sclr = 24000.0f / 2048.0f;
        int e0 = st * 5;
        float q0 = 0.f, q1 = 0.f, q2 = 0.f, q3 = 0.f, q4 = 0.f;
        if (e0     < CLEN) q0 = sP[refl_idx(e0)]     * sclr;
        if (e0 + 1 < CLEN) q1 = sP[refl_idx(e0 + 1)] * sclr;
        if (e0 + 2 < CLEN) q2 = sP[refl_idx(e0 + 2)] * sclr;
        if (e0 + 3 < CLEN) q3 = sP[refl_idx(e0 + 3)] * sclr;
        if (e0 + 4 < CLEN) q4 = sP[refl_idx(e0 + 4)] * sclr;

        float tsum = warp_sum(q0 + q1 + q2 + q3 + q4);
        if (lane == 0) red[w8] = tsum;
        __syncthreads();
        if (st == 0) {
            float a = 0.f;
#pragma unroll
            for (int i = 0; i < 8; i++) a += red[i];
            scl[0] = a;
        }
        __syncthreads();
        meanq = scl[0] * (1.0f / (float)CLEN);

        float p0, p1, p2, p3, p4;
        {
            int n0 = (e0     < CLEN);
            int n1 = (e0 + 1 < CLEN);
            int n2 = (e0 + 2 < CLEN);
            int n3 = (e0 + 3 < CLEN);
            int n4 = (e0 + 4 < CLEN);
            p0 = q0 - (n0 ? meanq : 0.f);
            p1 = p0 + q1 - (n1 ? meanq : 0.f);
            p2 = p1 + q2 - (n2 ? meanq : 0.f);
            p3 = p2 + q3 - (n3 ? meanq : 0.f);
            p4 = p3 + q4 - (n4 ? meanq : 0.f);
        }
        float ts = p4, s = ts;
#pragma unroll
        for (int o = 1; o < 32; o <<= 1) {
            float n = __shfl_up_sync(0xffffffffu, s, o);
            if (lane >= o) s += n;
        }
        if (lane == 31) wex[w8] = s;
        __syncthreads();
        if (st == 0) {
            float a = 0.f;
#pragma unroll
            for (int i = 0; i < 8; i++) { float t = wex[i]; wex[i] = a; a += t; }
        }
        __syncthreads();
        float off = wex[w8] + (s - ts);
        if (e0     < CLEN) sC[e0]     = off + p0;
        if (e0 + 1 < CLEN) sC[e0 + 1] = off + p1;
        if (e0 + 2 < CLEN) sC[e0 + 2] = off + p2;
        if (e0 + 3 < CLEN) sC[e0 + 3] = off + p3;
        if (e0 + 4 < CLEN) sC[e0 + 4] = off + p4;
        __syncthreads();
    }

    const float inv2048 = 1.0f / 2048.0f;
    const float slf    = 24000.0f / (PIF * f0v);
    const float pf0q   = PIF * f0v * (1.0f / 24000.0f);   // pi*f0/fs
    const float wbins    = f0v * (2.0f / 3.0f) * (2048.0f / 24000.0f);
    const float invwidth = 1.0f / (f0v * (2.0f / 3.0f));
    const float linpart  = meanq * wbins;

    // ======== TRANSFORM 2: DCT-I of G with smoothing fused into the build ====
    // G[k] is consumed exactly once (by its (n, 1024-n) pair owner), so it is
    // computed here directly from sC -- same total interp/log work, one less
    // SMEM round-trip and one less barrier than staging G in sP.
    {
        float e1p = 0.f;
        {
            int n = st + 1;                    // 1..256
            float gn = smoothG(sC, n,        wbins, invwidth, linpart);
            float gm = smoothG(sC, 1024 - n, wbins, invwidth, linpart);
            float d = gn - gm, a = 0.5f * (gn + gm);
            float s = __ldg(&g_sinb[n]);
            float c = __ldg(&g_sinb[512 - n]);
            zaf[n] = a - s * d;
            zaf[1024 - n] = a + s * d;
            e1p += c * d;
        }
        if (st <= 254) {
            int n = st + 257;                  // 257..511
            float gn = smoothG(sC, n,        wbins, invwidth, linpart);
            float gm = smoothG(sC, 1024 - n, wbins, invwidth, linpart);
            float d = gn - gm, a = 0.5f * (gn + gm);
            float s = __ldg(&g_sinb[n]);
            float c = __ldg(&g_sinb[512 - n]);
            zaf[n] = a - s * d;
            zaf[1024 - n] = a + s * d;
            e1p += c * d;
        }
        if (st == 0) {
            float g0 = smoothG(sC, 0,    wbins, invwidth, linpart);
            float gN = smoothG(sC, 1024, wbins, invwidth, linpart);
            zaf[0]   = 0.5f * (g0 + gN);
            zaf[512] = smoothG(sC, 512, wbins, invwidth, linpart);
            e1p += 0.5f * (g0 - gN);
        }
        e1p = warp_sum(e1p);
        if (lane == 0) red[w8] = e1p;
        __syncthreads();                       // orders zaf writes + sC reads
        if (st == 0) {
            float a = 0.f;
#pragma unroll
            for (int i = 0; i < 8; i++) a += red[i];
            scl[0] = 2.0f * a;                 // E1 (ordered by fft512 barriers)
        }
    }

    fft512(za, zb, tw3, st);                   // result in zb; za now dead

    // untangle rfft(y) -> even cepstrum outputs + ImY staging in zaf
    {
        int k = st;
        float2 Zk = zb[k];
        float2 Zm = zb[(512 - k) & 511];
        float Er = 0.5f * (Zk.x + Zm.x);
        float Ei = 0.5f * (Zk.y - Zm.y);
        float Or = 0.5f * (Zk.y + Zm.y);
        float Oi = 0.5f * (Zm.x - Zk.x);
        float2 w = __ldg(&g_twu[k]);
        float u = w.x * Or - w.y * Oi;
        float t = w.x * Oi + w.y * Or;
        float ReP = Er + u, ImP = Ei + t;
        float ReM = Er - u, ImM = t - Ei;
        if (k > 0) { zaf[k] = ImP; zaf[512 - k] = ImM; }
        else       { zaf[256] = -zb[256].y; zaf[512] = 0.f; }
        float lsE, lcE, sA, cA;
        __sincosf(pf0q * (float)(2 * k), &lsE, &lcE);
        __sincosf(pf0q * 1024.0f, &sA, &cA);
        int j = 2 * k, j2 = 1024 - 2 * k;
        float liftJ = (j == 0) ? 1.0f
                     : lsE * slf * __ldg(&g_invk[j]) * fmaf(0.6f, lsE * lsE, 1.0f);
        float ls2 = sA * lcE - cA * lsE;       // sin(pi*f0*j2/fs)
        float lift2 = ls2 * slf * __ldg(&g_invk[j2]) * fmaf(0.6f, ls2 * ls2, 1.0f);
        sP[j]  = 2.0f * ReP * inv2048 * liftJ;
        sP[j2] = 2.0f * ReM * inv2048 * lift2;
        if (k == 0) {
            float E512 = 2.0f * zb[256].x;
            float l5 = __sinf(pf0q * 512.0f);
            sP[512] = E512 * inv2048 * l5 * slf * __ldg(&g_invk[512])
                      * fmaf(0.6f, l5 * l5, 1.0f);
        }
    }
    __syncthreads();

    // scan of ImY -> odd cepstrum outputs
    {
        float E1v = scl[0];
        float v1 = zaf[2 * st + 1];
        float v2 = zaf[2 * st + 2];
        float p0 = v1, p1 = v1 + v2;
        float ts = p1, s = ts;
#pragma unroll
        for (int o = 1; o < 32; o <<= 1) {
            float n = __shfl_up_sync(0xffffffffu, s, o);
            if (lane >= o) s += n;
        }
        if (lane == 31) wex[w8] = s;
        __syncthreads();
        if (st == 0) {
            float a = 0.f;
#pragma unroll
            for (int i = 0; i < 8; i++) { float t = wex[i]; wex[i] = a; a += t; }
        }
        __syncthreads();
        float off = wex[w8] + (s - ts);
        {
            int o0 = 4 * st + 3;
            float E = E1v - 2.0f * (off + p0);
            float l = __sinf(pf0q * (float)o0);
            sP[o0] = E * inv2048 * l * slf * __ldg(&g_invk[o0]) * fmaf(0.6f, l * l, 1.0f);
        }
        if (st < 255) {
            int o1 = 4 * st + 5;
            float E = E1v - 2.0f * (off + p1);
            float l = __sinf(pf0q * (float)o1);
            sP[o1] = E * inv2048 * l * slf * __ldg(&g_invk[o1]) * fmaf(0.6f, l * l, 1.0f);
        }
        if (st == 0) {
            float l = __sinf(pf0q);
            sP[1] = E1v * inv2048 * l * slf * __ldg(&g_invk[1]) * fmaf(0.6f, l * l, 1.0f);
        }
    }
    __syncthreads();

    // ======== TRANSFORM 3: DCT-I of lifted cepstrum -> output ================
    {
        float e1p = 0.f;
        {
            int n = st + 1;
            float gn = sP[n], gm = sP[1024 - n];
            float d = gn - gm, a = 0.5f * (gn + gm);
            float s = __ldg(&g_sinb[n]);
            float c = __ldg(&g_sinb[512 - n]);
            zaf[n] = a - s * d;
            zaf[1024 - n] = a + s * d;
            e1p += c * d;
        }
        if (st <= 254) {
            int n = st + 257;
            float gn = sP[n], gm = sP[1024 - n];
            float d = gn - gm, a = 0.5f * (gn + gm);
            float s = __ldg(&g_sinb[n]);
            float c = __ldg(&g_sinb[512 - n]);
            zaf[n] = a - s * d;
            zaf[1024 - n] = a + s * d;
            e1p += c * d;
        }
        if (st == 0) {
            float g0 = sP[0], gN = sP[1024];
            zaf[0]   = 0.5f * (g0 + gN);
            zaf[512] = sP[512];
            e1p += 0.5f * (g0 - gN);
        }
        e1p = warp_sum(e1p);
        if (lane == 0) red[w8] = e1p;
        __syncthreads();                       // orders zaf writes before fft512
        if (st == 0) {
            float a = 0.f;
#pragma unroll
            for (int i = 0; i < 8; i++) a += red[i];
            scl[0] = 2.0f * a;                 // E1'
        }
    }

    fft512(za, zb, tw3, st);                   // result in zb

    float* op = out + ((size_t)b * NF + fi) * K1;

    {
        int k = st;
        float2 Zk = zb[k];
        float2 Zm = zb[(512 - k) & 511];
        float Er = 0.5f * (Zk.x + Zm.x);
        float Ei = 0.5f * (Zk.y - Zm.y);
        float Or = 0.5f * (Zk.y + Zm.y);
        float Oi = 0.5f * (Zm.x - Zk.x);
        float2 w = __ldg(&g_twu[k]);
        float u = w.x * Or - w.y * Oi;
        float t = w.x * Oi + w.y * Or;
        float ReP = Er + u, ImP = Ei + t;
        float ReM = Er - u, ImM = t - Ei;
        if (k > 0) { zaf[k] = ImP; zaf[512 - k] = ImM; }
        else       { zaf[256] = -zb[256].y; zaf[512] = 0.f; }
        if (dostore) {
            op[2 * k]        = 2.0f * ReP;
            op[1024 - 2 * k] = 2.0f * ReM;
            if (k == 0) op[512] = 2.0f * zb[256].x;
        }
    }
    __syncthreads();

    {
        float E1v = scl[0];
        float v1 = zaf[2 * st + 1];
        float v2 = zaf[2 * st + 2];
        float p0 = v1, p1 = v1 + v2;
        float ts = p1, s = ts;
#pragma unroll
        for (int o = 1; o < 32; o <<= 1) {
            float n = __shfl_up_sync(0xffffffffu, s, o);
            if (lane >= o) s += n;
        }
        if (lane == 31) wex[w8] = s;
        __syncthreads();
        if (st == 0) {
            float a = 0.f;
#pragma unroll
            for (int i = 0; i < 8; i++) { float t = wex[i]; wex[i] = a; a += t; }
        }
        __syncthreads();
        float off = wex[w8] + (s - ts);
        if (dostore) {
            op[4 * st + 3] = E1v - 2.0f * (off + p0);
            if (st < 255) op[4 * st + 5] = E1v - 2.0f * (off + p1);
            if (st == 0)  op[1] = E1v;
        }
    }
}

extern "C" void kernel_launch(void* const* d_in, const int* in_sizes, int n_in,
                              void* d_out, int out_size) {
    (void)in_sizes; (void)n_in; (void)out_size;
    const float* x  = (const float*)d_in[0];
    const float* f0 = (const float*)d_in[1];
    float* out = (float*)d_out;
    init_tables<<<5, 256>>>();
    cudaFuncSetAttribute(cheaptrick_kernel,
                         cudaFuncAttributeMaxDynamicSharedMemorySize, SMEM_BYTES);
    dim3 grid((NF + 1) / 2, BATCH);
    cheaptrick_kernel<<<grid, NTH, SMEM_BYTES>>>(x, f0, out);
}

// round 16
// speedup vs baseline: 1.7318x; 1.7318x over previous
#include <cuda_runtime.h>
#include <math.h>

#define BATCH 8
#define TLEN 120000
#define NF 1001
#define FFTL 2048
#define HALF 1024
#define K1 1025
#define KPAD 36
#define CLEN 1097          /* K1 + 2*KPAD */
#define NTH 256            /* one frame per CTA */
#define PIF 3.14159265358979f

/* dynamic smem layout (bytes), single frame:
   za  float2[1024] @ 0     (8192)
   zb  float2[1024] @ 8192  (8192)  -- sC alias during cumsum
   tw3 float2[504]  @ 16384 (4032)
   sP  float[1032]  @ 20416 (4128)
   wex float[8]     @ 24544 (32)
   red float[24]    @ 24576 (96)
   scl float[4]     @ 24672 (16)
   total 24688 -> 8 CTAs/SM (2048 threads = ceiling) */
#define SMEM_BYTES 24688

typedef unsigned long long u64;

__device__ float2 g_tw3[504];   // 126 (w1,w2,w3,pad) triples
__device__ float2 g_twu[257];   // e^{-i pi k/512}, k=0..256
__device__ float  g_sinb[513];  // sin(pi n/1024), n=0..512
__device__ float  g_invk[1025];

__global__ void init_tables() {
    int i = blockIdx.x * blockDim.x + threadIdx.x;
    if (i <= 1024) g_invk[i] = (i == 0) ? 0.0f : 1.0f / (float)i;
    if (i <= 256) {
        float s, c; sincospif(-(float)i * (1.0f / 512.0f), &s, &c);
        g_twu[i] = make_float2(c, s);
    }
    if (i <= 512) g_sinb[i] = sinpif((float)i * (1.0f / 1024.0f));
    if (i < 126) {
        float ang;  // w1 angle in units of pi
        if (i < 64)       ang = (float)(4 * i)          * (1.0f / 512.0f);
        else if (i < 80)  ang = (float)(16 * (i - 64))  * (1.0f / 512.0f);
        else if (i < 84)  ang = (float)(64 * (i - 80))  * (1.0f / 512.0f);
        else if (i < 116) ang = (float)(4 * (i - 84))   * (1.0f / 256.0f);
        else if (i < 124) ang = (float)(16 * (i - 116)) * (1.0f / 256.0f);
        else              ang = (float)(64 * (i - 124)) * (1.0f / 256.0f);
        float s1, c1, s2, c2, s3, c3;
        sincospif(-ang, &s1, &c1);
        sincospif(-2.0f * ang, &s2, &c2);
        sincospif(-3.0f * ang, &s3, &c3);
        g_tw3[4 * i]     = make_float2(c1, s1);
        g_tw3[4 * i + 1] = make_float2(c2, s2);
        g_tw3[4 * i + 2] = make_float2(c3, s3);
        g_tw3[4 * i + 3] = make_float2(0.f, 0.f);
    }
}

__device__ __forceinline__ float warp_sum(float v) {
#pragma unroll
    for (int o = 16; o; o >>= 1) v += __shfl_down_sync(0xffffffffu, v, o);
    return v;
}

__device__ __forceinline__ float2 cmul(float2 a, float2 b) {
    return make_float2(a.x * b.x - a.y * b.y, a.x * b.y + a.y * b.x);
}

__device__ __forceinline__ float2 padd(float2 a, float2 b) {
    float2 r;
    asm("{\n\t.reg .b64 ra, rb, rc;\n\t"
        "mov.b64 ra, {%2, %3};\n\t"
        "mov.b64 rb, {%4, %5};\n\t"
        "add.rn.f32x2 rc, ra, rb;\n\t"
        "mov.b64 {%0, %1}, rc;\n\t}"
        : "=f"(r.x), "=f"(r.y)
        : "f"(a.x), "f"(a.y), "f"(b.x), "f"(b.y));
    return r;
}

__device__ __forceinline__ float2 psub(float2 a, float2 b, u64 neg1) {
    float2 r;
    asm("{\n\t.reg .b64 ra, rb, rc;\n\t"
        "mov.b64 ra, {%2, %3};\n\t"
        "mov.b64 rb, {%4, %5};\n\t"
        "fma.rn.f32x2 rc, rb, %6, ra;\n\t"
        "mov.b64 {%0, %1}, rc;\n\t}"
        : "=f"(r.x), "=f"(r.y)
        : "f"(a.x), "f"(a.y), "f"(b.x), "f"(b.y), "l"(neg1));
    return r;
}

#define NEG1PK 0xBF800000BF800000ull

__device__ __forceinline__ int refl_idx(int t) {
    int j = t - KPAD;
    int r = j < 0 ? -j : j;
    if (r > HALF) r = FFTL - r;
    return r;
}

// radix-4 butterfly, stride 256 (1024-pt FFT)
__device__ __forceinline__ void bfly4(const float2* X, float2* Y, int r, int m,
                                      float2 w1, float2 w2, float2 w3) {
    const u64 n1 = NEG1PK;
    int q = r & (m - 1);
    int base = 4 * (r - q) + q;
    float2 a0 = X[r], a1 = X[r + 256], a2 = X[r + 512], a3 = X[r + 768];
    float2 b0 = padd(a0, a2), b1 = psub(a0, a2, n1);
    float2 b2 = padd(a1, a3), b3 = psub(a1, a3, n1);
    float2 t1 = make_float2(b1.x + b3.y, b1.y - b3.x);
    float2 t3 = make_float2(b1.x - b3.y, b1.y + b3.x);
    Y[base]         = padd(b0, b2);
    Y[base + m]     = cmul(t1, w1);
    Y[base + 2 * m] = cmul(psub(b0, b2, n1), w2);
    Y[base + 3 * m] = cmul(t3, w3);
}

// radix-4 butterfly, stride 128 (512-pt FFT)
__device__ __forceinline__ void bfly4s(const float2* X, float2* Y, int r, int m,
                                       float2 w1, float2 w2, float2 w3) {
    const u64 n1 = NEG1PK;
    int q = r & (m - 1);
    int base = 4 * (r - q) + q;
    float2 a0 = X[r], a1 = X[r + 128], a2 = X[r + 256], a3 = X[r + 384];
    float2 b0 = padd(a0, a2), b1 = psub(a0, a2, n1);
    float2 b2 = padd(a1, a3), b3 = psub(a1, a3, n1);
    float2 t1 = make_float2(b1.x + b3.y, b1.y - b3.x);
    float2 t3 = make_float2(b1.x - b3.y, b1.y + b3.x);
    Y[base]         = padd(b0, b2);
    Y[base + m]     = cmul(t1, w1);
    Y[base + 2 * m] = cmul(psub(b0, b2, n1), w2);
    Y[base + 3 * m] = cmul(t3, w3);
}

// Full 1024-pt complex FFT, radix-4 Stockham, 256 threads, 5 stages.
// Input in za, result in zb. w1s0 = per-thread stage-0 twiddle.
__device__ __forceinline__ void fft1024r4(float2* za, float2* zb,
                                          const float2* __restrict__ tw3,
                                          float2 w1s0, int r) {
    {   // stage 0: m=1, twiddle from registers
        float2 w1 = w1s0;
        float2 w2 = make_float2(w1.x * w1.x - w1.y * w1.y, 2.0f * w1.x * w1.y);
        float2 w3 = cmul(w1, w2);
        bfly4(za, zb, r, 1, w1, w2, w3);
    }
    __syncthreads();
    {
        int e = r >> 2;
        float4 w12 = ((const float4*)tw3)[2 * e];
        bfly4(zb, za, r, 4, make_float2(w12.x, w12.y), make_float2(w12.z, w12.w),
              tw3[4 * e + 2]);
    }
    __syncthreads();
    {
        int e = 64 + (r >> 4);
        float4 w12 = ((const float4*)tw3)[2 * e];
        bfly4(za, zb, r, 16, make_float2(w12.x, w12.y), make_float2(w12.z, w12.w),
              tw3[4 * e + 2]);
    }
    __syncthreads();
    {
        int e = 80 + (r >> 6);
        float4 w12 = ((const float4*)tw3)[2 * e];
        bfly4(zb, za, r, 64, make_float2(w12.x, w12.y), make_float2(w12.z, w12.w),
              tw3[4 * e + 2]);
    }
    __syncthreads();
    {   // stage 4: twiddles all 1
        const u64 n1 = NEG1PK;
        float2 a0 = za[r], a1 = za[r + 256], a2 = za[r + 512], a3 = za[r + 768];
        float2 b0 = padd(a0, a2), b1 = psub(a0, a2, n1);
        float2 b2 = padd(a1, a3), b3 = psub(a1, a3, n1);
        zb[r]       = padd(b0, b2);
        zb[r + 256] = make_float2(b1.x + b3.y, b1.y - b3.x);
        zb[r + 512] = psub(b0, b2, n1);
        zb[r + 768] = make_float2(b1.x - b3.y, b1.y + b3.x);
    }
    __syncthreads();
}

// Full 512-pt complex FFT: 4 radix-4 stages + final radix-2 (twiddle-free).
// Active on st<128; ALL threads must call (barriers inside). Result in zb.
__device__ __forceinline__ void fft512(float2* za, float2* zb,
                                       const float2* __restrict__ tw3, int st) {
    if (st < 128) {
        float2 w1 = __ldg(&g_twu[2 * st]);   // e^{-i pi st/256}
        float2 w2 = make_float2(w1.x * w1.x - w1.y * w1.y, 2.0f * w1.x * w1.y);
        float2 w3 = cmul(w1, w2);
        bfly4s(za, zb, st, 1, w1, w2, w3);
    }
    __syncthreads();
    if (st < 128) {
        int e = 84 + (st >> 2);
        float4 w12 = ((const float4*)tw3)[2 * e];
        bfly4s(zb, za, st, 4, make_float2(w12.x, w12.y), make_float2(w12.z, w12.w),
               tw3[4 * e + 2]);
    }
    __syncthreads();
    if (st < 128) {
        int e = 116 + (st >> 4);
        float4 w12 = ((const float4*)tw3)[2 * e];
        bfly4s(za, zb, st, 16, make_float2(w12.x, w12.y), make_float2(w12.z, w12.w),
               tw3[4 * e + 2]);
    }
    __syncthreads();
    if (st < 128) {
        int e = 124 + (st >> 6);
        float4 w12 = ((const float4*)tw3)[2 * e];
        bfly4s(zb, za, st, 64, make_float2(w12.x, w12.y), make_float2(w12.z, w12.w),
               tw3[4 * e + 2]);
    }
    __syncthreads();
    if (st < 128) {  // final radix-2, m=256, j=0 -> twiddle 1
        const u64 n1 = NEG1PK;
        float2 a0 = za[st],       c0 = za[st + 256];
        float2 a1 = za[st + 128], c1 = za[st + 384];
        zb[st]       = padd(a0, c0);
        zb[st + 256] = psub(a0, c0, n1);
        zb[st + 128] = padd(a1, c1);
        zb[st + 384] = psub(a1, c1, n1);
    }
    __syncthreads();
}

__device__ __forceinline__ float interpC(const float* __restrict__ C, float pos) {
    int lo = (int)floorf(pos);
    lo = min(max(lo, 0), CLEN - 2);
    float frac = pos - (float)lo;
    float clo = C[lo];
    return clo + (C[lo + 1] - clo) * frac;
}

__global__ __launch_bounds__(NTH, 8)
void cheaptrick_kernel(const float* __restrict__ x, const float* __restrict__ f0in,
                       float* __restrict__ out) {
    extern __shared__ char smem[];

    const int st   = threadIdx.x;
    const int lane = st & 31;
    const int w8   = st >> 5;
    const int fi   = blockIdx.x;
    const int b    = blockIdx.y;

    float2* za  = (float2*)(smem);
    float2* zb  = (float2*)(smem + 8192);
    float2* tw3 = (float2*)(smem + 16384);
    float*  sP  = (float*)(smem + 20416);
    float*  wex = (float*)(smem + 24544);
    float*  red = (float*)(smem + 24576);
    float*  scl = (float*)(smem + 24672);
    float*  sC  = (float*)(smem + 8192);   // aliases zb
    float*  zaf = (float*)za;

    float f0v = f0in[b * NF + fi];
    if (f0v <= 35.2078239f) f0v = 500.0f;   // F_MIN = 72000/2045

    // per-thread twiddles for the 1024-pt FFT + its untangle
    float2 wst, w1s0, wq;
    {
        float c, s;
        sincospif(-(float)st * (1.0f / 1024.0f), &s, &c);
        wst  = make_float2(c, s);
        w1s0 = make_float2(c * c - s * s, 2.0f * c * s);
        const float R2 = 0.70710678118654752f;
        wq   = cmul(wst, make_float2(R2, -R2));
    }

    for (int r = st; r < 504; r += NTH) tw3[r] = g_tw3[r];

    // -------- frame load + window (rotation recurrence) + sums ---------------
    const float hwl = rintf(36000.0f / f0v);
    const float f0n = f0v * (1.0f / 36000.0f);
    float cb, sb, cd, sd;
    sincospif((float)(st - HALF) * f0n, &sb, &cb);
    sincospif(256.0f * f0n, &sd, &cd);
    float s1 = 0.f, s2 = 0.f, s3 = 0.f;
    {
        float c0 = cb, s0 = sb;
#pragma unroll
        for (int ii = 0; ii < 8; ii++) {
            int i = st + ii * 256;
            int rel = i - HALF;
            int ix = min(max(fi * 120 + rel, 0), TLEN - 1);
            float v = x[b * TLEN + ix];
            float w = (fabsf((float)rel) <= hwl) ? fmaf(0.5f, c0, 0.5f) : 0.0f;
            zaf[i] = v * w;
            s1 += w; s2 += w * w; s3 += v * w;
            float cn = c0 * cd - s0 * sd;
            s0 = s0 * cd + c0 * sd;
            c0 = cn;
        }
    }
    s1 = warp_sum(s1); s2 = warp_sum(s2); s3 = warp_sum(s3);
    if (lane == 0) { red[w8] = s1; red[8 + w8] = s2; red[16 + w8] = s3; }
    __syncthreads();
    if (st == 0) {
        float a = 0.f, bb = 0.f, c = 0.f;
#pragma unroll
        for (int i = 0; i < 8; i++) { a += red[i]; bb += red[8 + i]; c += red[16 + i]; }
        scl[0] = a; scl[1] = bb; scl[2] = c;
    }
    __syncthreads();
    const float invs = 1.0f / sqrtf(scl[1]);
    const float mu   = scl[2] / scl[0];

    // -------- pack in place: wav = (v*w - mu*w)*invs (w replayed from regs) --
    {
        float c0 = cb, s0 = sb;
#pragma unroll
        for (int ii = 0; ii < 8; ii++) {
            int i = st + ii * 256;
            int rel = i - HALF;
            float w = (fabsf((float)rel) <= hwl) ? fmaf(0.5f, c0, 0.5f) : 0.0f;
            zaf[i] = (zaf[i] - mu * w) * invs;
            float cn = c0 * cd - s0 * sd;
            s0 = s0 * cd + c0 * sd;
            c0 = cn;
        }
    }
    __syncthreads();

    fft1024r4(za, zb, tw3, w1s0, st);   // result in zb

    // -------- paired untangle -> power spectrum ------------------------------
#pragma unroll
    for (int ii = 0; ii < 2; ii++) {
        int k = st + ii * 256;
        float2 w = (ii == 0) ? wst : wq;
        float2 Zk = zb[k];
        float2 Zm = zb[(1024 - k) & 1023];
        float Er = 0.5f * (Zk.x + Zm.x);
        float Ei = 0.5f * (Zk.y - Zm.y);
        float Or = 0.5f * (Zk.y + Zm.y);
        float Oi = 0.5f * (Zm.x - Zk.x);
        float u = w.x * Or - w.y * Oi;
        float t = w.x * Oi + w.y * Or;
        float XrP = Er + u, XiP = Ei + t;
        float XrM = Er - u, XiM = Ei - t;
        sP[k]        = XrP * XrP + XiP * XiP;
        sP[1024 - k] = XrM * XrM + XiM * XiM;
    }
    if (st == 0) { float2 Z = zb[512]; sP[512] = Z.x * Z.x + Z.y * Z.y; }
    __syncthreads();

    // -------- DC-band replication -------------------------------------------
    const float rate = f0v * (2048.0f / 24000.0f);
    const int  kmax  = (int)floorf(rate);
    float repl = 0.f;
    const bool dorep = (st <= kmax);
    if (dorep) {
        float m = rate - (float)st;
        int lo = (int)floorf(m);
        lo = min(max(lo, 0), K1 - 2);
        float fc = m - (float)lo;
        repl = sP[lo] * (1.f - fc) + sP[lo + 1] * fc;
    }
    __syncthreads();
    if (dorep) sP[st] += repl;
    __syncthreads();

    // -------- reflected cumsum, f32 with mean removal (sC aliases zb) --------
    float meanq;
    {
        const float sclr = 24000.0f / 2048.0f;
        int e0 = st * 5;
        float q0 = 0.f, q1 = 0.f, q2 = 0.f, q3 = 0.f, q4 = 0.f;
        if (e0     < CLEN) q0 = sP[refl_idx(e0)]     * sclr;
        if (e0 + 1 < CLEN) q1 = sP[refl_idx(e0 + 1)] * sclr;
        if (e0 + 2 < CLEN) q2 = sP[refl_idx(e0 + 2)] * sclr;
        if (e0 + 3 < CLEN) q3 = sP[refl_idx(e0 + 3)] * sclr;
        if (e0 + 4 < CLEN) q4 = sP[refl_idx(e0 + 4)] * sclr;

        float tsum = warp_sum(q0 + q1 + q2 + q3 + q4);
        if (lane == 0) red[w8] = tsum;
        __syncthreads();
        if (st == 0) {
            float a = 0.f;
#pragma unroll
            for (int i = 0; i < 8; i++) a += red[i];
            scl[0] = a;
        }
        __syncthreads();
        meanq = scl[0] * (1.0f / (float)CLEN);

        float p0, p1, p2, p3, p4;
        {
            int n0 = (e0     < CLEN);
            int n1 = (e0 + 1 < CLEN);
            int n2 = (e0 + 2 < CLEN);
            int n3 = (e0 + 3 < CLEN);
            int n4 = (e0 + 4 < CLEN);
            p0 = q0 - (n0 ? meanq : 0.f);
            p1 = p0 + q1 - (n1 ? meanq : 0.f);
            p2 = p1 + q2 - (n2 ? meanq : 0.f);
            p3 = p2 + q3 - (n3 ? meanq : 0.f);
            p4 = p3 + q4 - (n4 ? meanq : 0.f);
        }
        float ts = p4, s = ts;
#pragma unroll
        for (int o = 1; o < 32; o <<= 1) {
            float n = __shfl_up_sync(0xffffffffu, s, o);
            if (lane >= o) s += n;
        }
        if (lane == 31) wex[w8] = s;
        __syncthreads();
        if (st == 0) {
            float a = 0.f;
#pragma unroll
            for (int i = 0; i < 8; i++) { float t = wex[i]; wex[i] = a; a += t; }
        }
        __syncthreads();
        float off = wex[w8] + (s - ts);
        if (e0     < CLEN) sC[e0]     = off + p0;
        if (e0 + 1 < CLEN) sC[e0 + 1] = off + p1;
        if (e0 + 2 < CLEN) sC[e0 + 2] = off + p2;
        if (e0 + 3 < CLEN) sC[e0 + 3] = off + p3;
        if (e0 + 4 < CLEN) sC[e0 + 4] = off + p4;
        __syncthreads();
    }

    // -------- smoothing + log -> G in sP[0..1024] ----------------------------
    {
        const float wbins    = f0v * (2.0f / 3.0f) * (2048.0f / 24000.0f);
        const float invwidth = 1.0f / (f0v * (2.0f / 3.0f));
        const float linpart  = meanq * wbins;
        for (int k = st; k < K1; k += NTH) {
            float plo = (float)k - 0.5f * wbins + ((float)KPAD - 0.5f);
            float phi = plo + wbins;
            float Ps = (interpC(sC, phi) - interpC(sC, plo) + linpart) * invwidth;
            Ps = fmaxf(Ps, 1e-30f);
            sP[k] = __logf(Ps);
        }
        __syncthreads();
    }

    const float inv2048 = 1.0f / 2048.0f;
    const float slf    = 24000.0f / (PIF * f0v);
    const float pf0q   = PIF * f0v * (1.0f / 24000.0f);   // pi*f0/fs

    // ======== TRANSFORM 2: DCT-I of G (-> cepstrum) with lifter ==============
    // build y into za (all 256 threads) + E1 reduction
    {
        float e1p = 0.f;
        {
            int n = st + 1;                    // 1..256
            float gn = sP[n], gm = sP[1024 - n];
            float d = gn - gm, a = 0.5f * (gn + gm);
            float s = __ldg(&g_sinb[n]);
            float c = __ldg(&g_sinb[512 - n]);
            zaf[n] = a - s * d;
            zaf[1024 - n] = a + s * d;
            e1p += c * d;
        }
        if (st <= 254) {
            int n = st + 257;                  // 257..511
            float gn = sP[n], gm = sP[1024 - n];
            float d = gn - gm, a = 0.5f * (gn + gm);
            float s = __ldg(&g_sinb[n]);
            float c = __ldg(&g_sinb[512 - n]);
            zaf[n] = a - s * d;
            zaf[1024 - n] = a + s * d;
            e1p += c * d;
        }
        if (st == 0) {
            float g0 = sP[0], gN = sP[1024];
            zaf[0]   = 0.5f * (g0 + gN);
            zaf[512] = sP[512];
            e1p += 0.5f * (g0 - gN);
        }
        e1p = warp_sum(e1p);
        if (lane == 0) red[w8] = e1p;
        __syncthreads();
        if (st == 0) {
            float a = 0.f;
#pragma unroll
            for (int i = 0; i < 8; i++) a += red[i];
            scl[0] = 2.0f * a;                 // E1
        }
        __syncthreads();
    }

    fft512(za, zb, tw3, st);                   // result in zb; za now dead

    // untangle rfft(y) -> even cepstrum outputs + ImY staging in zaf
    {
        int k = st;
        float2 Zk = zb[k];
        float2 Zm = zb[(512 - k) & 511];
        float Er = 0.5f * (Zk.x + Zm.x);
        float Ei = 0.5f * (Zk.y - Zm.y);
        float Or = 0.5f * (Zk.y + Zm.y);
        float Oi = 0.5f * (Zm.x - Zk.x);
        float2 w = __ldg(&g_twu[k]);
        float u = w.x * Or - w.y * Oi;
        float t = w.x * Oi + w.y * Or;
        float ReP = Er + u, ImP = Ei + t;
        float ReM = Er - u, ImM = t - Ei;
        if (k > 0) { zaf[k] = ImP; zaf[512 - k] = ImM; }
        else       { zaf[256] = -zb[256].y; zaf[512] = 0.f; }
        float lsE, lcE, sA, cA;
        __sincosf(pf0q * (float)(2 * k), &lsE, &lcE);
        __sincosf(pf0q * 1024.0f, &sA, &cA);
        int j = 2 * k, j2 = 1024 - 2 * k;
        float liftJ = (j == 0) ? 1.0f
                     : lsE * slf * __ldg(&g_invk[j]) * fmaf(0.6f, lsE * lsE, 1.0f);
        float ls2 = sA * lcE - cA * lsE;       // sin(pi*f0*j2/fs)
        float lift2 = ls2 * slf * __ldg(&g_invk[j2]) * fmaf(0.6f, ls2 * ls2, 1.0f);
        sP[j]  = 2.0f * ReP * inv2048 * liftJ;
        sP[j2] = 2.0f * ReM * inv2048 * lift2;
        if (k == 0) {
            float E512 = 2.0f * zb[256].x;
            float l5 = __sinf(pf0q * 512.0f);
            sP[512] = E512 * inv2048 * l5 * slf * __ldg(&g_invk[512])
                      * fmaf(0.6f, l5 * l5, 1.0f);
        }
    }
    __syncthreads();

    // scan of ImY -> odd cepstrum outputs
    {
        float E1v = scl[0];
        float v1 = zaf[2 * st + 1];
        float v2 = zaf[2 * st + 2];
        float p0 = v1, p1 = v1 + v2;
        float ts = p1, s = ts;
#pragma unroll
        for (int o = 1; o < 32; o <<= 1) {
            float n = __shfl_up_sync(0xffffffffu, s, o);
            if (lane >= o) s += n;
        }
        if (lane == 31) wex[w8] = s;
        __syncthreads();
        if (st == 0) {
            float a = 0.f;
#pragma unroll
            for (int i = 0; i < 8; i++) { float t = wex[i]; wex[i] = a; a += t; }
        }
        __syncthreads();
        float off = wex[w8] + (s - ts);
        {
            int o0 = 4 * st + 3;
            float E = E1v - 2.0f * (off + p0);
            float l = __sinf(pf0q * (float)o0);
            sP[o0] = E * inv2048 * l * slf * __ldg(&g_invk[o0]) * fmaf(0.6f, l * l, 1.0f);
        }
        if (st < 255) {
            int o1 = 4 * st + 5;
            float E = E1v - 2.0f * (off + p1);
            float l = __sinf(pf0q * (float)o1);
            sP[o1] = E * inv2048 * l * slf * __ldg(&g_invk[o1]) * fmaf(0.6f, l * l, 1.0f);
        }
        if (st == 0) {
            float l = __sinf(pf0q);
            sP[1] = E1v * inv2048 * l * slf * __ldg(&g_invk[1]) * fmaf(0.6f, l * l, 1.0f);
        }
    }
    __syncthreads();

    // ======== TRANSFORM 3: DCT-I of lifted cepstrum -> output ================
    {
        float e1p = 0.f;
        {
            int n = st + 1;
            float gn = sP[n], gm = sP[1024 - n];
            float d = gn - gm, a = 0.5f * (gn + gm);
            float s = __ldg(&g_sinb[n]);
            float c = __ldg(&g_sinb[512 - n]);
            zaf[n] = a - s * d;
            zaf[1024 - n] = a + s * d;
            e1p += c * d;
        }
        if (st <= 254) {
            int n = st + 257;
            float gn = sP[n], gm = sP[1024 - n];
            float d = gn - gm, a = 0.5f * (gn + gm);
            float s = __ldg(&g_sinb[n]);
            float c = __ldg(&g_sinb[512 - n]);
            zaf[n] = a - s * d;
            zaf[1024 - n] = a + s * d;
            e1p += c * d;
        }
        if (st == 0) {
            float g0 = sP[0], gN = sP[1024];
            zaf[0]   = 0.5f * (g0 + gN);
            zaf[512] = sP[512];
            e1p += 0.5f * (g0 - gN);
        }
        e1p = warp_sum(e1p);
        if (lane == 0) red[w8] = e1p;
        __syncthreads();
        if (st == 0) {
            float a = 0.f;
#pragma unroll
            for (int i = 0; i < 8; i++) a += red[i];
            scl[0] = 2.0f * a;                 // E1'
        }
        __syncthreads();
    }

    fft512(za, zb, tw3, st);                   // result in zb

    float* op = out + ((size_t)b * NF + fi) * K1;

    {
        int k = st;
        float2 Zk = zb[k];
        float2 Zm = zb[(512 - k) & 511];
        float Er = 0.5f * (Zk.x + Zm.x);
        float Ei = 0.5f * (Zk.y - Zm.y);
        float Or = 0.5f * (Zk.y + Zm.y);
        float Oi = 0.5f * (Zm.x - Zk.x);
        float2 w = __ldg(&g_twu[k]);
        float u = w.x * Or - w.y * Oi;
        float t = w.x * Oi + w.y * Or;
        float ReP = Er + u, ImP = Ei + t;
        float ReM = Er - u, ImM = t - Ei;
        if (k > 0) { zaf[k] = ImP; zaf[512 - k] = ImM; }
        else       { zaf[256] = -zb[256].y; zaf[512] = 0.f; }
        op[2 * k]        = 2.0f * ReP;
        op[1024 - 2 * k] = 2.0f * ReM;
        if (k == 0) op[512] = 2.0f * zb[256].x;
    }
    __syncthreads();

    {
        float E1v = scl[0];
        float v1 = zaf[2 * st + 1];
        float v2 = zaf[2 * st + 2];
        float p0 = v1, p1 = v1 + v2;
        float ts = p1, s = ts;
#pragma unroll
        for (int o = 1; o < 32; o <<= 1) {
            float n = __shfl_up_sync(0xffffffffu, s, o);
            if (lane >= o) s += n;
        }
        if (lane == 31) wex[w8] = s;
        __syncthreads();
        if (st == 0) {
            float a = 0.f;
#pragma unroll
            for (int i = 0; i < 8; i++) { float t = wex[i]; wex[i] = a; a += t; }
        }
        __syncthreads();
        float off = wex[w8] + (s - ts);
        op[4 * st + 3] = E1v - 2.0f * (off + p0);
        if (st < 255) op[4 * st + 5] = E1v - 2.0f * (off + p1);
        if (st == 0)  op[1] = E1v;
    }
}

extern "C" void kernel_launch(void* const* d_in, const int* in_sizes, int n_in,
                              void* d_out, int out_size) {
    (void)in_sizes; (void)n_in; (void)out_size;
    const float* x  = (const float*)d_in[0];
    const float* f0 = (const float*)d_in[1];
    float* out = (float*)d_out;
    init_tables<<<5, 256>>>();
    cudaFuncSetAttribute(cheaptrick_kernel,
                         cudaFuncAttributeMaxDynamicSharedMemorySize, SMEM_BYTES);
    dim3 grid(NF, BATCH);
    cheaptrick_kernel<<<grid, NTH, SMEM_BYTES>>>(x, f0, out);
}

// round 17
// speedup vs baseline: 1.7557x; 1.0138x over previous
#include <cuda_runtime.h>
#include <math.h>

#define BATCH 8
#define TLEN 120000
#define NF 1001
#define FFTL 2048
#define HALF 1024
#define K1 1025
#define KPAD 36
#define CLEN 1097          /* K1 + 2*KPAD */
#define NTH 256            /* one frame per CTA */
#define PIF 3.14159265358979f

/* dynamic smem layout (bytes), single frame:
   za  float2[1024] @ 0     (8192)
   zb  float2[1024] @ 8192  (8192)  -- sC alias during cumsum
   tw3 float2[504]  @ 16384 (4032)
   sP  float[1032]  @ 20416 (4128)
   wex float[8]     @ 24544 (32)
   red float[24]    @ 24576 (96)
   scl float[4]     @ 24672 (16)
   total 24688 -> 8 CTAs/SM (2048 threads = ceiling) */
#define SMEM_BYTES 24688

typedef unsigned long long u64;

__device__ float2 g_tw3[504];   // 126 (w1,w2,w3,pad) triples
__device__ float2 g_twu[257];   // e^{-i pi k/512}, k=0..256
__device__ float  g_sinb[513];  // sin(pi n/1024), n=0..512
__device__ float  g_invk[1025];

__global__ void init_tables() {
    int i = blockIdx.x * blockDim.x + threadIdx.x;
    if (i <= 1024) g_invk[i] = (i == 0) ? 0.0f : 1.0f / (float)i;
    if (i <= 256) {
        float s, c; sincospif(-(float)i * (1.0f / 512.0f), &s, &c);
        g_twu[i] = make_float2(c, s);
    }
    if (i <= 512) g_sinb[i] = sinpif((float)i * (1.0f / 1024.0f));
    if (i < 126) {
        float ang;  // w1 angle in units of pi
        if (i < 64)       ang = (float)(4 * i)          * (1.0f / 512.0f);
        else if (i < 80)  ang = (float)(16 * (i - 64))  * (1.0f / 512.0f);
        else if (i < 84)  ang = (float)(64 * (i - 80))  * (1.0f / 512.0f);
        else if (i < 116) ang = (float)(4 * (i - 84))   * (1.0f / 256.0f);
        else if (i < 124) ang = (float)(16 * (i - 116)) * (1.0f / 256.0f);
        else              ang = (float)(64 * (i - 124)) * (1.0f / 256.0f);
        float s1, c1, s2, c2, s3, c3;
        sincospif(-ang, &s1, &c1);
        sincospif(-2.0f * ang, &s2, &c2);
        sincospif(-3.0f * ang, &s3, &c3);
        g_tw3[4 * i]     = make_float2(c1, s1);
        g_tw3[4 * i + 1] = make_float2(c2, s2);
        g_tw3[4 * i + 2] = make_float2(c3, s3);
        g_tw3[4 * i + 3] = make_float2(0.f, 0.f);
    }
}

__device__ __forceinline__ float warp_sum(float v) {
#pragma unroll
    for (int o = 16; o; o >>= 1) v += __shfl_down_sync(0xffffffffu, v, o);
    return v;
}

__device__ __forceinline__ float2 cmul(float2 a, float2 b) {
    return make_float2(a.x * b.x - a.y * b.y, a.x * b.y + a.y * b.x);
}

__device__ __forceinline__ float2 padd(float2 a, float2 b) {
    float2 r;
    asm("{\n\t.reg .b64 ra, rb, rc;\n\t"
        "mov.b64 ra, {%2, %3};\n\t"
        "mov.b64 rb, {%4, %5};\n\t"
        "add.rn.f32x2 rc, ra, rb;\n\t"
        "mov.b64 {%0, %1}, rc;\n\t}"
        : "=f"(r.x), "=f"(r.y)
        : "f"(a.x), "f"(a.y), "f"(b.x), "f"(b.y));
    return r;
}

__device__ __forceinline__ float2 psub(float2 a, float2 b, u64 neg1) {
    float2 r;
    asm("{\n\t.reg .b64 ra, rb, rc;\n\t"
        "mov.b64 ra, {%2, %3};\n\t"
        "mov.b64 rb, {%4, %5};\n\t"
        "fma.rn.f32x2 rc, rb, %6, ra;\n\t"
        "mov.b64 {%0, %1}, rc;\n\t}"
        : "=f"(r.x), "=f"(r.y)
        : "f"(a.x), "f"(a.y), "f"(b.x), "f"(b.y), "l"(neg1));
    return r;
}

#define NEG1PK 0xBF800000BF800000ull

__device__ __forceinline__ int refl_idx(int t) {
    int j = t - KPAD;
    int r = j < 0 ? -j : j;
    if (r > HALF) r = FFTL - r;
    return r;
}

// radix-4 butterfly, stride 256 (1024-pt FFT)
__device__ __forceinline__ void bfly4(const float2* X, float2* Y, int r, int m,
                                      float2 w1, float2 w2, float2 w3) {
    const u64 n1 = NEG1PK;
    int q = r & (m - 1);
    int base = 4 * (r - q) + q;
    float2 a0 = X[r], a1 = X[r + 256], a2 = X[r + 512], a3 = X[r + 768];
    float2 b0 = padd(a0, a2), b1 = psub(a0, a2, n1);
    float2 b2 = padd(a1, a3), b3 = psub(a1, a3, n1);
    float2 t1 = make_float2(b1.x + b3.y, b1.y - b3.x);
    float2 t3 = make_float2(b1.x - b3.y, b1.y + b3.x);
    Y[base]         = padd(b0, b2);
    Y[base + m]     = cmul(t1, w1);
    Y[base + 2 * m] = cmul(psub(b0, b2, n1), w2);
    Y[base + 3 * m] = cmul(t3, w3);
}

// radix-4 butterfly, stride 128 (512-pt FFT)
__device__ __forceinline__ void bfly4s(const float2* X, float2* Y, int r, int m,
                                       float2 w1, float2 w2, float2 w3) {
    const u64 n1 = NEG1PK;
    int q = r & (m - 1);
    int base = 4 * (r - q) + q;
    float2 a0 = X[r], a1 = X[r + 128], a2 = X[r + 256], a3 = X[r + 384];
    float2 b0 = padd(a0, a2), b1 = psub(a0, a2, n1);
    float2 b2 = padd(a1, a3), b3 = psub(a1, a3, n1);
    float2 t1 = make_float2(b1.x + b3.y, b1.y - b3.x);
    float2 t3 = make_float2(b1.x - b3.y, b1.y + b3.x);
    Y[base]         = padd(b0, b2);
    Y[base + m]     = cmul(t1, w1);
    Y[base + 2 * m] = cmul(psub(b0, b2, n1), w2);
    Y[base + 3 * m] = cmul(t3, w3);
}

// Full 1024-pt complex FFT, radix-4 Stockham, 256 threads, 5 stages.
// Input in za, result in zb. w1s0 = per-thread stage-0 twiddle.
__device__ __forceinline__ void fft1024r4(float2* za, float2* zb,
                                          const float2* __restrict__ tw3,
                                          float2 w1s0, int r) {
    {   // stage 0: m=1, twiddle from registers
        float2 w1 = w1s0;
        float2 w2 = make_float2(w1.x * w1.x - w1.y * w1.y, 2.0f * w1.x * w1.y);
        float2 w3 = cmul(w1, w2);
        bfly4(za, zb, r, 1, w1, w2, w3);
    }
    __syncthreads();
    {
        int e = r >> 2;
        float4 w12 = ((const float4*)tw3)[2 * e];
        bfly4(zb, za, r, 4, make_float2(w12.x, w12.y), make_float2(w12.z, w12.w),
              tw3[4 * e + 2]);
    }
    __syncthreads();
    {
        int e = 64 + (r >> 4);
        float4 w12 = ((const float4*)tw3)[2 * e];
        bfly4(za, zb, r, 16, make_float2(w12.x, w12.y), make_float2(w12.z, w12.w),
              tw3[4 * e + 2]);
    }
    __syncthreads();
    {
        int e = 80 + (r >> 6);
        float4 w12 = ((const float4*)tw3)[2 * e];
        bfly4(zb, za, r, 64, make_float2(w12.x, w12.y), make_float2(w12.z, w12.w),
              tw3[4 * e + 2]);
    }
    __syncthreads();
    {   // stage 4: twiddles all 1
        const u64 n1 = NEG1PK;
        float2 a0 = za[r], a1 = za[r + 256], a2 = za[r + 512], a3 = za[r + 768];
        float2 b0 = padd(a0, a2), b1 = psub(a0, a2, n1);
        float2 b2 = padd(a1, a3), b3 = psub(a1, a3, n1);
        zb[r]       = padd(b0, b2);
        zb[r + 256] = make_float2(b1.x + b3.y, b1.y - b3.x);
        zb[r + 512] = psub(b0, b2, n1);
        zb[r + 768] = make_float2(b1.x - b3.y, b1.y + b3.x);
    }
    __syncthreads();
}

// Full 512-pt complex FFT: 4 radix-4 stages + final radix-2 (twiddle-free).
// Active on st<128; ALL threads must call (barriers inside). Result in zb.
__device__ __forceinline__ void fft512(float2* za, float2* zb,
                                       const float2* __restrict__ tw3, int st) {
    if (st < 128) {
        float2 w1 = __ldg(&g_twu[2 * st]);   // e^{-i pi st/256}
        float2 w2 = make_float2(w1.x * w1.x - w1.y * w1.y, 2.0f * w1.x * w1.y);
        float2 w3 = cmul(w1, w2);
        bfly4s(za, zb, st, 1, w1, w2, w3);
    }
    __syncthreads();
    if (st < 128) {
        int e = 84 + (st >> 2);
        float4 w12 = ((const float4*)tw3)[2 * e];
        bfly4s(zb, za, st, 4, make_float2(w12.x, w12.y), make_float2(w12.z, w12.w),
               tw3[4 * e + 2]);
    }
    __syncthreads();
    if (st < 128) {
        int e = 116 + (st >> 4);
        float4 w12 = ((const float4*)tw3)[2 * e];
        bfly4s(za, zb, st, 16, make_float2(w12.x, w12.y), make_float2(w12.z, w12.w),
               tw3[4 * e + 2]);
    }
    __syncthreads();
    if (st < 128) {
        int e = 124 + (st >> 6);
        float4 w12 = ((const float4*)tw3)[2 * e];
        bfly4s(zb, za, st, 64, make_float2(w12.x, w12.y), make_float2(w12.z, w12.w),
               tw3[4 * e + 2]);
    }
    __syncthreads();
    if (st < 128) {  // final radix-2, m=256, j=0 -> twiddle 1
        const u64 n1 = NEG1PK;
        float2 a0 = za[st],       c0 = za[st + 256];
        float2 a1 = za[st + 128], c1 = za[st + 384];
        zb[st]       = padd(a0, c0);
        zb[st + 256] = psub(a0, c0, n1);
        zb[st + 128] = padd(a1, c1);
        zb[st + 384] = psub(a1, c1, n1);
    }
    __syncthreads();
}

__device__ __forceinline__ float interpC(const float* __restrict__ C, float pos) {
    int lo = (int)floorf(pos);
    lo = min(max(lo, 0), CLEN - 2);
    float frac = pos - (float)lo;
    float clo = C[lo];
    return clo + (C[lo + 1] - clo) * frac;
}

__global__ __launch_bounds__(NTH, 8)
void cheaptrick_kernel(const float* __restrict__ x, const float* __restrict__ f0in,
                       float* __restrict__ out) {
    extern __shared__ char smem[];

    const int st   = threadIdx.x;
    const int lane = st & 31;
    const int w8   = st >> 5;
    const int fi   = blockIdx.x;
    const int b    = blockIdx.y;

    float2* za  = (float2*)(smem);
    float2* zb  = (float2*)(smem + 8192);
    float2* tw3 = (float2*)(smem + 16384);
    float*  sP  = (float*)(smem + 20416);
    float*  wex = (float*)(smem + 24544);
    float*  red = (float*)(smem + 24576);
    float*  scl = (float*)(smem + 24672);
    float*  sC  = (float*)(smem + 8192);   // aliases zb
    float*  zaf = (float*)za;

    float f0v = f0in[b * NF + fi];
    if (f0v <= 35.2078239f) f0v = 500.0f;   // F_MIN = 72000/2045

    // per-thread twiddles for the 1024-pt FFT + its untangle
    float2 wst, w1s0, wq;
    {
        float c, s;
        sincospif(-(float)st * (1.0f / 1024.0f), &s, &c);
        wst  = make_float2(c, s);
        w1s0 = make_float2(c * c - s * s, 2.0f * c * s);
        const float R2 = 0.70710678118654752f;
        wq   = cmul(wst, make_float2(R2, -R2));
    }

    for (int r = st; r < 504; r += NTH) tw3[r] = g_tw3[r];

    // -------- pass A: window + sums only (no SMEM writes) --------------------
    const float hwl = rintf(36000.0f / f0v);
    const float f0n = f0v * (1.0f / 36000.0f);
    float cb, sb, cd, sd;
    sincospif((float)(st - HALF) * f0n, &sb, &cb);
    sincospif(256.0f * f0n, &sd, &cd);
    float s1 = 0.f, s2 = 0.f, s3 = 0.f;
    {
        float c0 = cb, s0 = sb;
#pragma unroll
        for (int ii = 0; ii < 8; ii++) {
            int i = st + ii * 256;
            int rel = i - HALF;
            int ix = min(max(fi * 120 + rel, 0), TLEN - 1);
            float v = x[b * TLEN + ix];
            float w = (fabsf((float)rel) <= hwl) ? fmaf(0.5f, c0, 0.5f) : 0.0f;
            s1 += w; s2 += w * w; s3 += v * w;
            float cn = c0 * cd - s0 * sd;
            s0 = s0 * cd + c0 * sd;
            c0 = cn;
        }
    }
    s1 = warp_sum(s1); s2 = warp_sum(s2); s3 = warp_sum(s3);
    if (lane == 0) { red[w8] = s1; red[8 + w8] = s2; red[16 + w8] = s3; }
    __syncthreads();
    if (st == 0) {
        float a = 0.f, bb = 0.f, c = 0.f;
#pragma unroll
        for (int i = 0; i < 8; i++) { a += red[i]; bb += red[8 + i]; c += red[16 + i]; }
        scl[0] = a; scl[1] = bb; scl[2] = c;
    }
    __syncthreads();
    const float invs = 1.0f / sqrtf(scl[1]);
    const float mu   = scl[2] / scl[0];

    // -------- pass B: reload v (L1-hit) + single packed store ----------------
    {
        float c0 = cb, s0 = sb;
#pragma unroll
        for (int ii = 0; ii < 8; ii++) {
            int i = st + ii * 256;
            int rel = i - HALF;
            int ix = min(max(fi * 120 + rel, 0), TLEN - 1);
            float v = x[b * TLEN + ix];
            float w = (fabsf((float)rel) <= hwl) ? fmaf(0.5f, c0, 0.5f) : 0.0f;
            zaf[i] = (v * w - mu * w) * invs;
            float cn = c0 * cd - s0 * sd;
            s0 = s0 * cd + c0 * sd;
            c0 = cn;
        }
    }
    __syncthreads();

    fft1024r4(za, zb, tw3, w1s0, st);   // result in zb

    // -------- paired untangle -> power spectrum ------------------------------
#pragma unroll
    for (int ii = 0; ii < 2; ii++) {
        int k = st + ii * 256;
        float2 w = (ii == 0) ? wst : wq;
        float2 Zk = zb[k];
        float2 Zm = zb[(1024 - k) & 1023];
        float Er = 0.5f * (Zk.x + Zm.x);
        float Ei = 0.5f * (Zk.y - Zm.y);
        float Or = 0.5f * (Zk.y + Zm.y);
        float Oi = 0.5f * (Zm.x - Zk.x);
        float u = w.x * Or - w.y * Oi;
        float t = w.x * Oi + w.y * Or;
        float XrP = Er + u, XiP = Ei + t;
        float XrM = Er - u, XiM = Ei - t;
        sP[k]        = XrP * XrP + XiP * XiP;
        sP[1024 - k] = XrM * XrM + XiM * XiM;
    }
    if (st == 0) { float2 Z = zb[512]; sP[512] = Z.x * Z.x + Z.y * Z.y; }
    __syncthreads();

    // -------- DC-band replication -------------------------------------------
    const float rate = f0v * (2048.0f / 24000.0f);
    const int  kmax  = (int)floorf(rate);
    float repl = 0.f;
    const bool dorep = (st <= kmax);
    if (dorep) {
        float m = rate - (float)st;
        int lo = (int)floorf(m);
        lo = min(max(lo, 0), K1 - 2);
        float fc = m - (float)lo;
        repl = sP[lo] * (1.f - fc) + sP[lo + 1] * fc;
    }
    __syncthreads();
    if (dorep) sP[st] += repl;
    __syncthreads();

    // -------- reflected cumsum, f32 with mean removal (sC aliases zb) --------
    float meanq;
    {
        const float sclr = 24000.0f / 2048.0f;
        int e0 = st * 5;
        float q0 = 0.f, q1 = 0.f, q2 = 0.f, q3 = 0.f, q4 = 0.f;
        if (e0     < CLEN) q0 = sP[refl_idx(e0)]     * sclr;
        if (e0 + 1 < CLEN) q1 = sP[refl_idx(e0 + 1)] * sclr;
        if (e0 + 2 < CLEN) q2 = sP[refl_idx(e0 + 2)] * sclr;
        if (e0 + 3 < CLEN) q3 = sP[refl_idx(e0 + 3)] * sclr;
        if (e0 + 4 < CLEN) q4 = sP[refl_idx(e0 + 4)] * sclr;

        float tsum = warp_sum(q0 + q1 + q2 + q3 + q4);
        if (lane == 0) red[w8] = tsum;
        __syncthreads();
        if (st == 0) {
            float a = 0.f;
#pragma unroll
            for (int i = 0; i < 8; i++) a += red[i];
            scl[0] = a;
        }
        __syncthreads();
        meanq = scl[0] * (1.0f / (float)CLEN);

        float p0, p1, p2, p3, p4;
        {
            int n0 = (e0     < CLEN);
            int n1 = (e0 + 1 < CLEN);
            int n2 = (e0 + 2 < CLEN);
            int n3 = (e0 + 3 < CLEN);
            int n4 = (e0 + 4 < CLEN);
            p0 = q0 - (n0 ? meanq : 0.f);
            p1 = p0 + q1 - (n1 ? meanq : 0.f);
            p2 = p1 + q2 - (n2 ? meanq : 0.f);
            p3 = p2 + q3 - (n3 ? meanq : 0.f);
            p4 = p3 + q4 - (n4 ? meanq : 0.f);
        }
        float ts = p4, s = ts;
#pragma unroll
        for (int o = 1; o < 32; o <<= 1) {
            float n = __shfl_up_sync(0xffffffffu, s, o);
            if (lane >= o) s += n;
        }
        if (lane == 31) wex[w8] = s;
        __syncthreads();
        if (st == 0) {
            float a = 0.f;
#pragma unroll
            for (int i = 0; i < 8; i++) { float t = wex[i]; wex[i] = a; a += t; }
        }
        __syncthreads();
        float off = wex[w8] + (s - ts);
        if (e0     < CLEN) sC[e0]     = off + p0;
        if (e0 + 1 < CLEN) sC[e0 + 1] = off + p1;
        if (e0 + 2 < CLEN) sC[e0 + 2] = off + p2;
        if (e0 + 3 < CLEN) sC[e0 + 3] = off + p3;
        if (e0 + 4 < CLEN) sC[e0 + 4] = off + p4;
        __syncthreads();
    }

    // -------- smoothing + log -> G in sP[0..1024] ----------------------------
    {
        const float wbins    = f0v * (2.0f / 3.0f) * (2048.0f / 24000.0f);
        const float invwidth = 1.0f / (f0v * (2.0f / 3.0f));
        const float linpart  = meanq * wbins;
        for (int k = st; k < K1; k += NTH) {
            float plo = (float)k - 0.5f * wbins + ((float)KPAD - 0.5f);
            float phi = plo + wbins;
            float Ps = (interpC(sC, phi) - interpC(sC, plo) + linpart) * invwidth;
            Ps = fmaxf(Ps, 1e-30f);
            sP[k] = __logf(Ps);
        }
        __syncthreads();
    }

    const float inv2048 = 1.0f / 2048.0f;
    const float slf    = 24000.0f / (PIF * f0v);
    const float pf0q   = PIF * f0v * (1.0f / 24000.0f);   // pi*f0/fs

    // ======== TRANSFORM 2: DCT-I of G (-> cepstrum) with lifter ==============
    // build y into za (all 256 threads) + E1 reduction
    {
        float e1p = 0.f;
        {
            int n = st + 1;                    // 1..256
            float gn = sP[n], gm = sP[1024 - n];
            float d = gn - gm, a = 0.5f * (gn + gm);
            float s = __ldg(&g_sinb[n]);
            float c = __ldg(&g_sinb[512 - n]);
            zaf[n] = a - s * d;
            zaf[1024 - n] = a + s * d;
            e1p += c * d;
        }
        if (st <= 254) {
            int n = st + 257;                  // 257..511
            float gn = sP[n], gm = sP[1024 - n];
            float d = gn - gm, a = 0.5f * (gn + gm);
            float s = __ldg(&g_sinb[n]);
            float c = __ldg(&g_sinb[512 - n]);
            zaf[n] = a - s * d;
            zaf[1024 - n] = a + s * d;
            e1p += c * d;
        }
        if (st == 0) {
            float g0 = sP[0], gN = sP[1024];
            zaf[0]   = 0.5f * (g0 + gN);
            zaf[512] = sP[512];
            e1p += 0.5f * (g0 - gN);
        }
        e1p = warp_sum(e1p);
        if (lane == 0) red[w8] = e1p;
        __syncthreads();                       // orders zaf writes + red writes
        if (st == 0) {
            float a = 0.f;
#pragma unroll
            for (int i = 0; i < 8; i++) a += red[i];
            scl[0] = 2.0f * a;                 // E1 (ordered by fft512 barriers)
        }
    }

    fft512(za, zb, tw3, st);                   // result in zb; za now dead

    // untangle rfft(y) -> even cepstrum outputs + ImY staging in zaf
    {
        int k = st;
        float2 Zk = zb[k];
        float2 Zm = zb[(512 - k) & 511];
        float Er = 0.5f * (Zk.x + Zm.x);
        float Ei = 0.5f * (Zk.y - Zm.y);
        float Or = 0.5f * (Zk.y + Zm.y);
        float Oi = 0.5f * (Zm.x - Zk.x);
        float2 w = __ldg(&g_twu[k]);
        float u = w.x * Or - w.y * Oi;
        float t = w.x * Oi + w.y * Or;
        float ReP = Er + u, ImP = Ei + t;
        float ReM = Er - u, ImM = t - Ei;
        if (k > 0) { zaf[k] = ImP; zaf[512 - k] = ImM; }
        else       { zaf[256] = -zb[256].y; zaf[512] = 0.f; }
        float lsE, lcE, sA, cA;
        __sincosf(pf0q * (float)(2 * k), &lsE, &lcE);
        __sincosf(pf0q * 1024.0f, &sA, &cA);
        int j = 2 * k, j2 = 1024 - 2 * k;
        float liftJ = (j == 0) ? 1.0f
                     : lsE * slf * __ldg(&g_invk[j]) * fmaf(0.6f, lsE * lsE, 1.0f);
        float ls2 = sA * lcE - cA * lsE;       // sin(pi*f0*j2/fs)
        float lift2 = ls2 * slf * __ldg(&g_invk[j2]) * fmaf(0.6f, ls2 * ls2, 1.0f);
        sP[j]  = 2.0f * ReP * inv2048 * liftJ;
        sP[j2] = 2.0f * ReM * inv2048 * lift2;
        if (k == 0) {
            float E512 = 2.0f * zb[256].x;
            float l5 = __sinf(pf0q * 512.0f);
            sP[512] = E512 * inv2048 * l5 * slf * __ldg(&g_invk[512])
                      * fmaf(0.6f, l5 * l5, 1.0f);
        }
    }
    __syncthreads();

    // scan of ImY -> odd cepstrum outputs
    {
        float E1v = scl[0];
        float v1 = zaf[2 * st + 1];
        float v2 = zaf[2 * st + 2];
        float p0 = v1, p1 = v1 + v2;
        float ts = p1, s = ts;
#pragma unroll
        for (int o = 1; o < 32; o <<= 1) {
            float n = __shfl_up_sync(0xffffffffu, s, o);
            if (lane >= o) s += n;
        }
        if (lane == 31) wex[w8] = s;
        __syncthreads();
        if (st == 0) {
            float a = 0.f;
#pragma unroll
            for (int i = 0; i < 8; i++) { float t = wex[i]; wex[i] = a; a += t; }
        }
        __syncthreads();
        float off = wex[w8] + (s - ts);
        {
            int o0 = 4 * st + 3;
            float E = E1v - 2.0f * (off + p0);
            float l = __sinf(pf0q * (float)o0);
            sP[o0] = E * inv2048 * l * slf * __ldg(&g_invk[o0]) * fmaf(0.6f, l * l, 1.0f);
        }
        if (st < 255) {
            int o1 = 4 * st + 5;
            float E = E1v - 2.0f * (off + p1);
            float l = __sinf(pf0q * (float)o1);
            sP[o1] = E * inv2048 * l * slf * __ldg(&g_invk[o1]) * fmaf(0.6f, l * l, 1.0f);
        }
        if (st == 0) {
            float l = __sinf(pf0q);
            sP[1] = E1v * inv2048 * l * slf * __ldg(&g_invk[1]) * fmaf(0.6f, l * l, 1.0f);
        }
    }
    __syncthreads();

    // ======== TRANSFORM 3: DCT-I of lifted cepstrum -> output ================
    {
        float e1p = 0.f;
        {
            int n = st + 1;
            float gn = sP[n], gm = sP[1024 - n];
            float d = gn - gm, a = 0.5f * (gn + gm);
            float s = __ldg(&g_sinb[n]);
            float c = __ldg(&g_sinb[512 - n]);
            zaf[n] = a - s * d;
            zaf[1024 - n] = a + s * d;
            e1p += c * d;
        }
        if (st <= 254) {
            int n = st + 257;
            float gn = sP[n], gm = sP[1024 - n];
            float d = gn - gm, a = 0.5f * (gn + gm);
            float s = __ldg(&g_sinb[n]);
            float c = __ldg(&g_sinb[512 - n]);
            zaf[n] = a - s * d;
            zaf[1024 - n] = a + s * d;
            e1p += c * d;
        }
        if (st == 0) {
            float g0 = sP[0], gN = sP[1024];
            zaf[0]   = 0.5f * (g0 + gN);
            zaf[512] = sP[512];
            e1p += 0.5f * (g0 - gN);
        }
        e1p = warp_sum(e1p);
        if (lane == 0) red[w8] = e1p;
        __syncthreads();                       // orders zaf writes + red writes
        if (st == 0) {
            float a = 0.f;
#pragma unroll
            for (int i = 0; i < 8; i++) a += red[i];
            scl[0] = 2.0f * a;                 // E1'
        }
    }

    fft512(za, zb, tw3, st);                   // result in zb

    float* op = out + ((size_t)b * NF + fi) * K1;

    {
        int k = st;
        float2 Zk = zb[k];
        float2 Zm = zb[(512 - k) & 511];
        float Er = 0.5f * (Zk.x + Zm.x);
        float Ei = 0.5f * (Zk.y - Zm.y);
        float Or = 0.5f * (Zk.y + Zm.y);
        float Oi = 0.5f * (Zm.x - Zk.x);
        float2 w = __ldg(&g_twu[k]);
        float u = w.x * Or - w.y * Oi;
        float t = w.x * Oi + w.y * Or;
        float ReP = Er + u, ImP = Ei + t;
        float ReM = Er - u, ImM = t - Ei;
        if (k > 0) { zaf[k] = ImP; zaf[512 - k] = ImM; }
        else       { zaf[256] = -zb[256].y; zaf[512] = 0.f; }
        op[2 * k]        = 2.0f * ReP;
        op[1024 - 2 * k] = 2.0f * ReM;
        if (k == 0) op[512] = 2.0f * zb[256].x;
    }
    __syncthreads();

    {
        float E1v = scl[0];
        float v1 = zaf[2 * st + 1];
        float v2 = zaf[2 * st + 2];
        float p0 = v1, p1 = v1 + v2;
        float ts = p1, s = ts;
#pragma unroll
        for (int o = 1; o < 32; o <<= 1) {
            float n = __shfl_up_sync(0xffffffffu, s, o);
            if (lane >= o) s += n;
        }
        if (lane == 31) wex[w8] = s;
        __syncthreads();
        if (st == 0) {
            float a = 0.f;
#pragma unroll
            for (int i = 0; i < 8; i++) { float t = wex[i]; wex[i] = a; a += t; }
        }
        __syncthreads();
        float off = wex[w8] + (s - ts);
        op[4 * st + 3] = E1v - 2.0f * (off + p0);
        if (st < 255) op[4 * st + 5] = E1v - 2.0f * (off + p1);
        if (st == 0)  op[1] = E1v;
    }
}

extern "C" void kernel_launch(void* const* d_in, const int* in_sizes, int n_in,
                              void* d_out, int out_size) {
    (void)in_sizes; (void)n_in; (void)out_size;
    const float* x  = (const float*)d_in[0];
    const float* f0 = (const float*)d_in[1];
    float* out = (float*)d_out;
    init_tables<<<5, 256>>>();
    cudaFuncSetAttribute(cheaptrick_kernel,
                         cudaFuncAttributeMaxDynamicSharedMemorySize, SMEM_BYTES);
    dim3 grid(NF, BATCH);
    cheaptrick_kernel<<<grid, NTH, SMEM_BYTES>>>(x, f0, out);
}